// round 1
// baseline (speedup 1.0000x reference)
#include <cuda_runtime.h>

// StrictOrthogonal via CholeskyQR2 on complex 16384x32.
// Q (QR factor, positive-real R diagonal) is unique; reference's MGS + 3
// half-step refinement sweeps converge to the same Q to ~1e-7 (kappa ~ 1.09),
// far inside the 1e-3 rel_err threshold.

#define M_ROWS 16384
#define R_COLS 32
#define CHUNK  128
#define NCTA_GRAM (M_ROWS / CHUNK)   // 128

// Scratch (device globals; no allocation allowed in kernel_launch)
__device__ float  g_part[NCTA_GRAM * 2048];   // per-CTA Gram partials (1 MB)
__device__ float2 g_S[R_COLS * R_COLS];       // reduced Gram (Hermitian)
__device__ float2 g_W[R_COLS * R_COLS];       // W = R^{-1} (upper triangular)
__device__ float2 g_A1[M_ROWS * R_COLS];      // intermediate A * R1^{-1} (4 MB)

// ---------------------------------------------------------------------------
// Gram: S = A^H A  (partial per CTA, deterministic — no atomics)
// 128 CTAs x 256 threads. Each CTA handles one 128-row chunk.
// Threads: 4 groups of 64; each group is an 8x8 grid of 4x4 complex tiles
// covering the full 32x32 output over its 32 rows.
// ---------------------------------------------------------------------------
__global__ __launch_bounds__(256) void gram_kernel(const float2* __restrict__ A) {
    __shared__ float smem[8192];                       // 32 KB, dual-purpose
    float2* sA = reinterpret_cast<float2*>(smem);      // [CHUNK][32]
    const int tid = threadIdx.x;
    const int blk = blockIdx.x;

    // Stage chunk: 128 rows * 32 complex = 2048 float4
    {
        const float4* src = reinterpret_cast<const float4*>(A + (size_t)blk * CHUNK * R_COLS);
        float4* dst = reinterpret_cast<float4*>(smem);
#pragma unroll
        for (int i = 0; i < 8; ++i) dst[tid + 256 * i] = src[tid + 256 * i];
    }
    __syncthreads();

    const int g  = tid >> 6;        // group 0..3 (rows [g*32, g*32+32))
    const int t  = tid & 63;
    const int ti = t & 7;
    const int tj = t >> 3;
    const int i0 = ti * 4;
    const int j0 = tj * 4;
    const int r0 = g * 32;

    float2 acc[4][4];
#pragma unroll
    for (int p = 0; p < 4; ++p)
#pragma unroll
        for (int q = 0; q < 4; ++q) acc[p][q] = make_float2(0.f, 0.f);

#pragma unroll 4
    for (int r = 0; r < 32; ++r) {
        const float4* rowp = reinterpret_cast<const float4*>(&sA[(r0 + r) * R_COLS]);
        float4 av0 = rowp[ti * 2], av1 = rowp[ti * 2 + 1];
        float4 bv0 = rowp[tj * 2], bv1 = rowp[tj * 2 + 1];
        float2 a[4] = { {av0.x, av0.y}, {av0.z, av0.w}, {av1.x, av1.y}, {av1.z, av1.w} };
        float2 b[4] = { {bv0.x, bv0.y}, {bv0.z, bv0.w}, {bv1.x, bv1.y}, {bv1.z, bv1.w} };
#pragma unroll
        for (int p = 0; p < 4; ++p)
#pragma unroll
            for (int q = 0; q < 4; ++q) {
                // acc += conj(a) * b
                acc[p][q].x = fmaf(a[p].x, b[q].x, acc[p][q].x);
                acc[p][q].x = fmaf(a[p].y, b[q].y, acc[p][q].x);
                acc[p][q].y = fmaf(a[p].x, b[q].y, acc[p][q].y);
                acc[p][q].y = fmaf(-a[p].y, b[q].x, acc[p][q].y);
            }
    }
    __syncthreads();   // finished reading sA; reuse smem for group partials

#pragma unroll
    for (int p = 0; p < 4; ++p)
#pragma unroll
        for (int q = 0; q < 4; ++q) {
            int e = ((i0 + p) * R_COLS + (j0 + q)) * 2;
            smem[g * 2048 + e]     = acc[p][q].x;
            smem[g * 2048 + e + 1] = acc[p][q].y;
        }
    __syncthreads();

    // Combine the 4 groups (fixed order) and write CTA partial contiguously.
#pragma unroll
    for (int k = 0; k < 8; ++k) {
        int e = tid + 256 * k;
        g_part[blk * 2048 + e] =
            (smem[e] + smem[2048 + e]) + (smem[4096 + e] + smem[6144 + e]);
    }
}

// ---------------------------------------------------------------------------
// Deterministic fixed-order reduction of 128 partials -> g_S
// 8 CTAs x 256 threads; thread e sums column e across all partial blocks.
// ---------------------------------------------------------------------------
__global__ __launch_bounds__(256) void reduce_kernel() {
    int e = blockIdx.x * 256 + threadIdx.x;   // 0..2047
    float s0 = 0.f, s1 = 0.f, s2 = 0.f, s3 = 0.f;
#pragma unroll 4
    for (int b = 0; b < NCTA_GRAM; b += 4) {
        s0 += g_part[(b + 0) * 2048 + e];
        s1 += g_part[(b + 1) * 2048 + e];
        s2 += g_part[(b + 2) * 2048 + e];
        s3 += g_part[(b + 3) * 2048 + e];
    }
    reinterpret_cast<float*>(g_S)[e] = (s0 + s1) + (s2 + s3);
}

// ---------------------------------------------------------------------------
// Warp-parallel complex Cholesky S = L L^H (lane r owns row r), then
// column-parallel forward substitution T = L^{-1} (lane c owns column c),
// then write W = T^H = R^{-1} (upper triangular; exact zeros below diag).
// 1 CTA x 32 threads.
// ---------------------------------------------------------------------------
__global__ __launch_bounds__(32) void cholinv_kernel() {
    const unsigned FULL = 0xffffffffu;
    const int r = threadIdx.x;

    float2 row[R_COLS];
#pragma unroll
    for (int c = 0; c < R_COLS; ++c) row[c] = g_S[r * R_COLS + c];

    __shared__ float2 L[R_COLS][R_COLS];

#pragma unroll
    for (int k = 0; k < R_COLS; ++k) {
        float dkk  = __shfl_sync(FULL, row[k].x, k);   // real positive diagonal
        float invs = 1.0f / sqrtf(dkk);
        float2 l;                                      // L[r][k] (valid for r>=k)
        l.x = row[k].x * invs;
        l.y = row[k].y * invs;
        row[k] = l;
#pragma unroll
        for (int j = k + 1; j < R_COLS; ++j) {
            float lx = __shfl_sync(FULL, l.x, j);      // L[j][k]
            float ly = __shfl_sync(FULL, l.y, j);
            // row[j] -= l * conj(L[j][k])
            row[j].x -= l.x * lx + l.y * ly;
            row[j].y -= l.y * lx - l.x * ly;
        }
    }

#pragma unroll
    for (int k = 0; k < R_COLS; ++k) L[r][k] = row[k];
    __syncwarp();

    // Forward substitution: solve L x = e_c  (x = column c of T = L^{-1})
    const int c = r;
    float2 x[R_COLS];
#pragma unroll
    for (int rr = 0; rr < R_COLS; ++rr) {
        float2 s = (rr == c) ? make_float2(1.f, 0.f) : make_float2(0.f, 0.f);
#pragma unroll
        for (int k = 0; k < rr; ++k) {
            float2 lv = L[rr][k];
            s.x -= lv.x * x[k].x - lv.y * x[k].y;
            s.y -= lv.x * x[k].y + lv.y * x[k].x;
        }
        float invd = 1.0f / L[rr][rr].x;
        x[rr] = make_float2(s.x * invd, s.y * invd);
    }

    // W[c][j] = conj(T[j][c]);  x[j] = 0 for j < c so W is exactly upper tri.
#pragma unroll
    for (int j = 0; j < R_COLS; ++j)
        g_W[c * R_COLS + j] = make_float2(x[j].x, -x[j].y);
}

// ---------------------------------------------------------------------------
// Apply: Out[m][:] = A[m][:] * W   (W upper triangular, broadcast from SMEM)
// 128 CTAs x 128 threads; one row per thread.
// ---------------------------------------------------------------------------
__global__ __launch_bounds__(128) void apply_kernel(const float2* __restrict__ A,
                                                    float2* __restrict__ Out) {
    __shared__ float2 sW[R_COLS * R_COLS];
    const int tid = threadIdx.x;
    {
        const float4* wsrc = reinterpret_cast<const float4*>(g_W);
        float4* wdst = reinterpret_cast<float4*>(sW);
#pragma unroll
        for (int i = 0; i < 4; ++i) wdst[tid + 128 * i] = wsrc[tid + 128 * i];
    }
    __syncthreads();

    const int m = blockIdx.x * 128 + tid;
    const float4* src = reinterpret_cast<const float4*>(A + (size_t)m * R_COLS);
    float2 a[R_COLS];
#pragma unroll
    for (int i = 0; i < 16; ++i) {
        float4 v = src[i];
        a[2 * i]     = make_float2(v.x, v.y);
        a[2 * i + 1] = make_float2(v.z, v.w);
    }

    float2* outp = Out + (size_t)m * R_COLS;
#pragma unroll
    for (int j = 0; j < R_COLS; ++j) {
        float2 s = make_float2(0.f, 0.f);
#pragma unroll
        for (int i = 0; i <= j; ++i) {     // W is upper triangular
            float2 w = sW[i * R_COLS + j];
            s.x = fmaf(a[i].x, w.x, s.x);
            s.x = fmaf(-a[i].y, w.y, s.x);
            s.y = fmaf(a[i].x, w.y, s.y);
            s.y = fmaf(a[i].y, w.x, s.y);
        }
        outp[j] = s;
    }
}

// ---------------------------------------------------------------------------
extern "C" void kernel_launch(void* const* d_in, const int* in_sizes, int n_in,
                              void* d_out, int out_size) {
    (void)in_sizes; (void)n_in; (void)out_size;
    const float2* A = reinterpret_cast<const float2*>(d_in[0]);
    float2* Out = reinterpret_cast<float2*>(d_out);

    float2* A1 = nullptr;
    cudaGetSymbolAddress(reinterpret_cast<void**>(&A1), g_A1);

    // ---- pass 1: A1 = A * R1^{-1} ----
    gram_kernel<<<NCTA_GRAM, 256>>>(A);
    reduce_kernel<<<8, 256>>>();
    cholinv_kernel<<<1, 32>>>();
    apply_kernel<<<128, 128>>>(A, A1);

    // ---- pass 2: Out = A1 * R2^{-1}  (CholeskyQR2 cleanup) ----
    gram_kernel<<<NCTA_GRAM, 256>>>(A1);
    reduce_kernel<<<8, 256>>>();
    cholinv_kernel<<<1, 32>>>();
    apply_kernel<<<128, 128>>>(A1, Out);
}